// round 9
// baseline (speedup 1.0000x reference)
#include <cuda_runtime.h>
#include <cuda_bf16.h>
#include <stdint.h>

#define BATCH 4096
#define SEQT  256
#define DIN0  128
#define HID   64
#define G3    192
#define MTOT  (BATCH * SEQT)   // 1048576 rows

// Scratch (static: no allocations allowed)
__device__ float g_gx[(long)MTOT * G3];   // gate preactivations incl. b_ih (reused both layers)
__device__ float g_h1[(long)MTOT * HID];  // layer-1 hidden sequence

typedef unsigned long long u64;
typedef unsigned int u32;

// ---------------------------------------------------------------- common
__device__ __forceinline__ void mma16816(float* c, const u32* a, const u32* b) {
    asm volatile(
        "mma.sync.aligned.m16n8k16.row.col.f32.bf16.bf16.f32 "
        "{%0,%1,%2,%3}, {%4,%5,%6,%7}, {%8,%9}, {%0,%1,%2,%3};"
        : "+f"(c[0]), "+f"(c[1]), "+f"(c[2]), "+f"(c[3])
        : "r"(a[0]), "r"(a[1]), "r"(a[2]), "r"(a[3]), "r"(b[0]), "r"(b[1]));
}
__device__ __forceinline__ u32 packhi(float a, float b) {
    return ((u32)__bfloat16_as_ushort(__float2bfloat16(a)))
         | ((u32)__bfloat16_as_ushort(__float2bfloat16(b)) << 16);
}
__device__ __forceinline__ u32 packlo(float a, float b) {
    float al = a - __bfloat162float(__float2bfloat16(a));
    float bl = b - __bfloat162float(__float2bfloat16(b));
    return ((u32)__bfloat16_as_ushort(__float2bfloat16(al)))
         | ((u32)__bfloat16_as_ushort(__float2bfloat16(bl)) << 16);
}
__device__ __forceinline__ float tanha(float x) {
    float y;
    asm("tanh.approx.f32 %0, %1;" : "=f"(y) : "f"(x));
    return y;
}
__device__ __forceinline__ float siga(float x) {       // sigmoid via tanh (1 MUFU)
    return fmaf(0.5f, tanha(0.5f * x), 0.5f);
}

// ================================================================= GEMM
// OUT[m][n] = sum_k X[m][k] * W[n][k] + bias[n], split-bf16 3-term HMMA.
// Persistent; B staged+split once; M=64 tiles, A double-buffered. (passed R6-R8)
template<int K>
__global__ __launch_bounds__(256, 1)
void proj_gemm(const float* __restrict__ X,
               const float* __restrict__ W,
               const float* __restrict__ bias,
               float* __restrict__ OUT)
{
    constexpr int P      = K + 8;
    constexpr int NTILES = MTOT / 64;
    constexpr int ABUF   = 64 * P * 2;
    constexpr int BBUF   = G3 * P * 2;
    constexpr int NPF    = K / 16;

    extern __shared__ char smem[];
    char* Bh    = smem;
    char* Bl    = Bh + BBUF;
    char* Abase = Bl + BBUF;

    const int tid = threadIdx.x;
    const int wid = tid >> 5;
    const int lid = tid & 31;
    const int g   = lid >> 2;
    const int cp  = lid & 3;
    const int GRID = gridDim.x;

    for (int c = tid; c < G3 * (K / 8); c += 256) {
        int row = c / (K / 8), k = (c % (K / 8)) * 8;
        const float4* src = (const float4*)(W + row * K + k);
        float4 v0 = src[0], v1 = src[1];
        int byte = (row * P + k) * 2;
        *(uint4*)(Bh + byte) = make_uint4(packhi(v0.x, v0.y), packhi(v0.z, v0.w),
                                          packhi(v1.x, v1.y), packhi(v1.z, v1.w));
        *(uint4*)(Bl + byte) = make_uint4(packlo(v0.x, v0.y), packlo(v0.z, v0.w),
                                          packlo(v1.x, v1.y), packlo(v1.z, v1.w));
    }

    const int mrow = (wid & 1) * 32;
    const int ncol = (wid >> 1) * 48;

    float breg[6][2];
#pragma unroll
    for (int nt = 0; nt < 6; nt++) {
        int col = ncol + nt * 8 + 2 * cp;
        breg[nt][0] = bias[col];
        breg[nt][1] = bias[col + 1];
    }

    float4 pfA[NPF];
    long tile0 = blockIdx.x;
    if (tile0 < NTILES) {
#pragma unroll
        for (int q = 0; q < NPF; q++) {
            int idx = tid + 256 * q;
            int row = idx / (K / 4), k = (idx % (K / 4)) * 4;
            pfA[q] = *(const float4*)(X + (tile0 * 64 + row) * K + k);
        }
        char* Ah = Abase;
        char* Al = Abase + ABUF;
#pragma unroll
        for (int q = 0; q < NPF; q++) {
            int idx = tid + 256 * q;
            int row = idx / (K / 4), k = (idx % (K / 4)) * 4;
            float4 v = pfA[q];
            int byte = (row * P + k) * 2;
            *(uint2*)(Ah + byte) = make_uint2(packhi(v.x, v.y), packhi(v.z, v.w));
            *(uint2*)(Al + byte) = make_uint2(packlo(v.x, v.y), packlo(v.z, v.w));
        }
    }
    __syncthreads();

    int it = 0;
    for (long tile = tile0; tile < NTILES; tile += GRID, it++) {
        const long nxt = tile + GRID;
        if (nxt < NTILES) {
#pragma unroll
            for (int q = 0; q < NPF; q++) {
                int idx = tid + 256 * q;
                int row = idx / (K / 4), k = (idx % (K / 4)) * 4;
                pfA[q] = *(const float4*)(X + (nxt * 64 + row) * K + k);
            }
        }

        char* Ah = Abase + (it & 1) * 2 * ABUF;
        char* Al = Ah + ABUF;

        float acc[2][6][4];
#pragma unroll
        for (int mt = 0; mt < 2; mt++)
#pragma unroll
            for (int nt = 0; nt < 6; nt++)
#pragma unroll
                for (int q = 0; q < 4; q++) acc[mt][nt][q] = 0.0f;

#pragma unroll
        for (int ks = 0; ks < K / 16; ks++) {
            const int kb = ks * 16;
            u32 ahf[2][4], alf[2][4];
#pragma unroll
            for (int mt = 0; mt < 2; mt++) {
                int r = mrow + mt * 16 + g;
                int c0b = (r * P + kb + 2 * cp) * 2;
                int c1b = ((r + 8) * P + kb + 2 * cp) * 2;
                ahf[mt][0] = *(const u32*)(Ah + c0b);
                ahf[mt][1] = *(const u32*)(Ah + c1b);
                ahf[mt][2] = *(const u32*)(Ah + c0b + 16);
                ahf[mt][3] = *(const u32*)(Ah + c1b + 16);
                alf[mt][0] = *(const u32*)(Al + c0b);
                alf[mt][1] = *(const u32*)(Al + c1b);
                alf[mt][2] = *(const u32*)(Al + c0b + 16);
                alf[mt][3] = *(const u32*)(Al + c1b + 16);
            }
            u32 bhf[6][2], blf[6][2];
#pragma unroll
            for (int nt = 0; nt < 6; nt++) {
                int n = ncol + nt * 8 + g;
                int bb = (n * P + kb + 2 * cp) * 2;
                bhf[nt][0] = *(const u32*)(Bh + bb);
                bhf[nt][1] = *(const u32*)(Bh + bb + 16);
                blf[nt][0] = *(const u32*)(Bl + bb);
                blf[nt][1] = *(const u32*)(Bl + bb + 16);
            }
#pragma unroll
            for (int mt = 0; mt < 2; mt++)
#pragma unroll
                for (int nt = 0; nt < 6; nt++) {
                    mma16816(acc[mt][nt], ahf[mt], bhf[nt]);
                    mma16816(acc[mt][nt], ahf[mt], blf[nt]);
                    mma16816(acc[mt][nt], alf[mt], bhf[nt]);
                }
        }

#pragma unroll
        for (int mt = 0; mt < 2; mt++) {
            long r0 = tile * 64 + mrow + mt * 16 + g;
#pragma unroll
            for (int nt = 0; nt < 6; nt++) {
                int col = ncol + nt * 8 + 2 * cp;
                *(float2*)(OUT + r0 * G3 + col) =
                    make_float2(acc[mt][nt][0] + breg[nt][0], acc[mt][nt][1] + breg[nt][1]);
                *(float2*)(OUT + (r0 + 8) * G3 + col) =
                    make_float2(acc[mt][nt][2] + breg[nt][0], acc[mt][nt][3] + breg[nt][1]);
            }
        }

        if (nxt < NTILES) {
            char* nAh = Abase + ((it + 1) & 1) * 2 * ABUF;
            char* nAl = nAh + ABUF;
#pragma unroll
            for (int q = 0; q < NPF; q++) {
                int idx = tid + 256 * q;
                int row = idx / (K / 4), k = (idx % (K / 4)) * 4;
                float4 v = pfA[q];
                int byte = (row * P + k) * 2;
                *(uint2*)(nAh + byte) = make_uint2(packhi(v.x, v.y), packhi(v.z, v.w));
                *(uint2*)(nAl + byte) = make_uint2(packlo(v.x, v.y), packlo(v.z, v.w));
            }
        }
        __syncthreads();
    }
}

// ============================================================ recurrence (HMMA, in-register gates)
// Per CTA: 32 rows in 2 groups of 16 (warps 0-3 / 4-7, named barriers, stagger).
// Warp j of a group owns n8-tiles {2j,2j+1, 8+2j,9+2j, 16+2j,17+2j} -> its
// fragments hold r,z,n for units [16j,16j+16): gates computed IN REGISTERS
// from acc, no gh SMEM staging. b_hh folded into acc init. W_hh in B-fragment
// registers (hi/lo bf16, 3-term, numerics unchanged from R7/R8).
#define BBR 32
#define NTR 256
#define PAB 144                // A-tile byte pitch; conflict-free
#define PHF 68                 // fp32 h buffer pitch (FC epilogue only)

template<bool FIRST>
__global__ __launch_bounds__(NTR, 1)
void gru_hmma(const float* __restrict__ GX,   // [MTOT][G3] x-part preact + b_ih
              const float* __restrict__ Whh,  // [G3][HID]
              const float* __restrict__ bhh,  // [G3]
              const float* __restrict__ Wfc,
              const float* __restrict__ bfc,
              float* __restrict__ hout,       // FIRST: g_h1
              float* __restrict__ out)        // !FIRST: [BATCH]
{
    extern __shared__ char smemc[];
    char*  sAh = smemc;                        // [32][PAB] bf16 hi
    char*  sAl = sAh + BBR * PAB;              // bf16 lo
    float* sHf = (float*)(sAl + BBR * PAB);    // [32][PHF] fp32 h (FC epilogue)

    const int tid = threadIdx.x;
    const int wid = tid >> 5;
    const int lid = tid & 31;
    const int g   = lid >> 2;
    const int cp  = lid & 3;
    const int b0  = blockIdx.x * BBR;

    const int grp  = wid >> 2;                 // 0 or 1
    const int j    = wid & 3;                  // warp within group
    const int mrow = grp * 16;

    // n8-tile bases for this warp: r,r,z,z,n,n
    int n0t[6];
    n0t[0] = 16 * j;        n0t[1] = 16 * j + 8;
    n0t[2] = 64 + 16 * j;   n0t[3] = 64 + 16 * j + 8;
    n0t[4] = 128 + 16 * j;  n0t[5] = 128 + 16 * j + 8;

    // ---- W_hh B-fragments (hi/lo) + b_hh per column, loaded once ----
    u32 bh[4][6][2], bl[4][6][2];
    float bhv[6][2];
#pragma unroll
    for (int nt = 0; nt < 6; nt++) {
        int n = n0t[nt] + g;
#pragma unroll
        for (int kc = 0; kc < 4; kc++) {
            int k0 = kc * 16 + 2 * cp;
            float w0 = Whh[n * HID + k0],     w1 = Whh[n * HID + k0 + 1];
            float w2 = Whh[n * HID + k0 + 8], w3 = Whh[n * HID + k0 + 9];
            bh[kc][nt][0] = packhi(w0, w1);  bh[kc][nt][1] = packhi(w2, w3);
            bl[kc][nt][0] = packlo(w0, w1);  bl[kc][nt][1] = packlo(w2, w3);
        }
        bhv[nt][0] = bhh[n0t[nt] + 2 * cp];
        bhv[nt][1] = bhh[n0t[nt] + 2 * cp + 1];
    }

    // thread's gate slots: rows ra, rb; unit pairs p0..p0+1, p1..p1+1
    const int p0 = 16 * j + 2 * cp;
    const int p1 = p0 + 8;
    const int ra = mrow + g;
    const int rb = ra + 8;
    const long gba = ((long)(b0 + ra) * SEQT) * G3;
    const long gbb = ((long)(b0 + rb) * SEQT) * G3;

    float hreg[8];
#pragma unroll
    for (int s = 0; s < 8; s++) hreg[s] = 0.0f;

    // zero A tiles (h0 = 0)
    for (int i = tid; i < BBR * PAB / 4; i += NTR) {
        ((u32*)sAh)[i] = 0u;
        ((u32*)sAl)[i] = 0u;
    }
    __syncthreads();

    // prefetch gx(t=0): [row a/b][gate r,z,n][pair p0,p1] as float2
    float2 pf[12];
    {
        const float* A = GX + gba;
        const float* B = GX + gbb;
        pf[0] = *(const float2*)(A + p0);        pf[1] = *(const float2*)(A + p1);
        pf[2] = *(const float2*)(A + 64 + p0);   pf[3] = *(const float2*)(A + 64 + p1);
        pf[4] = *(const float2*)(A + 128 + p0);  pf[5] = *(const float2*)(A + 128 + p1);
        pf[6] = *(const float2*)(B + p0);        pf[7] = *(const float2*)(B + p1);
        pf[8] = *(const float2*)(B + 64 + p0);   pf[9] = *(const float2*)(B + 64 + p1);
        pf[10] = *(const float2*)(B + 128 + p0); pf[11] = *(const float2*)(B + 128 + p1);
    }

    if (grp == 1) __nanosleep(400);            // phase stagger
    const u32 barid = grp + 1;

    for (int t = 0; t < SEQT; t++) {
        // ---------- MMA phase: acc = Whh . h + b_hh ----------
        float acc[6][4];
#pragma unroll
        for (int nt = 0; nt < 6; nt++) {
            acc[nt][0] = bhv[nt][0]; acc[nt][1] = bhv[nt][1];
            acc[nt][2] = bhv[nt][0]; acc[nt][3] = bhv[nt][1];
        }
#pragma unroll
        for (int kc = 0; kc < 4; kc++) {
            const int kb = kc * 16;
            u32 ahf[4], alf[4];
            {
                int c0b = ra * PAB + (kb + 2 * cp) * 2;
                int c1b = rb * PAB + (kb + 2 * cp) * 2;
                ahf[0] = *(const u32*)(sAh + c0b);
                ahf[1] = *(const u32*)(sAh + c1b);
                ahf[2] = *(const u32*)(sAh + c0b + 16);
                ahf[3] = *(const u32*)(sAh + c1b + 16);
                alf[0] = *(const u32*)(sAl + c0b);
                alf[1] = *(const u32*)(sAl + c1b);
                alf[2] = *(const u32*)(sAl + c0b + 16);
                alf[3] = *(const u32*)(sAl + c1b + 16);
            }
#pragma unroll
            for (int nt = 0; nt < 6; nt++) {
                mma16816(acc[nt], ahf, bh[kc][nt]);
                mma16816(acc[nt], ahf, bl[kc][nt]);
                mma16816(acc[nt], alf, bh[kc][nt]);
            }
        }
        // all group warps finished reading sA
        asm volatile("bar.sync %0, 128;" :: "r"(barid) : "memory");

        // ---------- gate phase (pure registers) ----------
        {
            float h[8];
            // row ra (q = 0,1), row rb (q = 2,3)
#pragma unroll
            for (int half = 0; half < 2; half++) {
                int qb = half * 2;          // acc q-offset for this row
                int pb = half * 6;          // pf offset for this row
#pragma unroll
                for (int pi = 0; pi < 2; pi++) {     // pair p0 / p1
                    float gr0 = (pi ? pf[pb + 1].x : pf[pb + 0].x);
                    float gr1 = (pi ? pf[pb + 1].y : pf[pb + 0].y);
                    float gz0 = (pi ? pf[pb + 3].x : pf[pb + 2].x);
                    float gz1 = (pi ? pf[pb + 3].y : pf[pb + 2].y);
                    float gn0 = (pi ? pf[pb + 5].x : pf[pb + 4].x);
                    float gn1 = (pi ? pf[pb + 5].y : pf[pb + 4].y);
                    int nt = pi;            // r tiles 0/1, z tiles 2/3, n tiles 4/5
                    float rg0 = siga(gr0 + acc[nt][qb]);
                    float rg1 = siga(gr1 + acc[nt][qb + 1]);
                    float zg0 = siga(gz0 + acc[nt + 2][qb]);
                    float zg1 = siga(gz1 + acc[nt + 2][qb + 1]);
                    float ng0 = tanha(gn0 + rg0 * acc[nt + 4][qb]);
                    float ng1 = tanha(gn1 + rg1 * acc[nt + 4][qb + 1]);
                    int s = half * 4 + pi * 2;
                    h[s]     = ng0 + zg0 * (hreg[s]     - ng0);
                    h[s + 1] = ng1 + zg1 * (hreg[s + 1] - ng1);
                    hreg[s] = h[s]; hreg[s + 1] = h[s + 1];
                }
            }
            // write h (bf16 hi/lo) into A tile
            *(u32*)(sAh + ra * PAB + p0 * 2) = packhi(h[0], h[1]);
            *(u32*)(sAh + ra * PAB + p1 * 2) = packhi(h[2], h[3]);
            *(u32*)(sAh + rb * PAB + p0 * 2) = packhi(h[4], h[5]);
            *(u32*)(sAh + rb * PAB + p1 * 2) = packhi(h[6], h[7]);
            *(u32*)(sAl + ra * PAB + p0 * 2) = packlo(h[0], h[1]);
            *(u32*)(sAl + ra * PAB + p1 * 2) = packlo(h[2], h[3]);
            *(u32*)(sAl + rb * PAB + p0 * 2) = packlo(h[4], h[5]);
            *(u32*)(sAl + rb * PAB + p1 * 2) = packlo(h[6], h[7]);

            if (FIRST) {
                float* ha = hout + ((long)(b0 + ra) * SEQT + t) * HID;
                float* hb = hout + ((long)(b0 + rb) * SEQT + t) * HID;
                *(float2*)(ha + p0) = make_float2(h[0], h[1]);
                *(float2*)(ha + p1) = make_float2(h[2], h[3]);
                *(float2*)(hb + p0) = make_float2(h[4], h[5]);
                *(float2*)(hb + p1) = make_float2(h[6], h[7]);
            }
            // prefetch gx(t+1)
            if (t + 1 < SEQT) {
                const float* A = GX + gba + (long)(t + 1) * G3;
                const float* B = GX + gbb + (long)(t + 1) * G3;
                pf[0] = *(const float2*)(A + p0);        pf[1] = *(const float2*)(A + p1);
                pf[2] = *(const float2*)(A + 64 + p0);   pf[3] = *(const float2*)(A + 64 + p1);
                pf[4] = *(const float2*)(A + 128 + p0);  pf[5] = *(const float2*)(A + 128 + p1);
                pf[6] = *(const float2*)(B + p0);        pf[7] = *(const float2*)(B + p1);
                pf[8] = *(const float2*)(B + 64 + p0);   pf[9] = *(const float2*)(B + 64 + p1);
                pf[10] = *(const float2*)(B + 128 + p0); pf[11] = *(const float2*)(B + 128 + p1);
            }
        }
        // h writes visible before next MMA phase reads
        asm volatile("bar.sync %0, 128;" :: "r"(barid) : "memory");
    }

    // ---- final FC (layer 2) ----
    if (!FIRST) {
        sHf[ra * PHF + p0]     = hreg[0];
        sHf[ra * PHF + p0 + 1] = hreg[1];
        sHf[ra * PHF + p1]     = hreg[2];
        sHf[ra * PHF + p1 + 1] = hreg[3];
        sHf[rb * PHF + p0]     = hreg[4];
        sHf[rb * PHF + p0 + 1] = hreg[5];
        sHf[rb * PHF + p1]     = hreg[6];
        sHf[rb * PHF + p1 + 1] = hreg[7];
        __syncthreads();
        if (tid < BBR) {
            float s = bfc[0];
#pragma unroll
            for (int u = 0; u < HID; u++) s += sHf[tid * PHF + u] * Wfc[u];
            out[b0 + tid] = s;
        }
    }
}

// ================================================================= host
extern "C" void kernel_launch(void* const* d_in, const int* in_sizes, int n_in,
                              void* d_out, int out_size)
{
    const float* x    = (const float*)d_in[0];
    const float* Wih0 = (const float*)d_in[1];
    const float* Whh0 = (const float*)d_in[2];
    const float* bih0 = (const float*)d_in[3];
    const float* bhh0 = (const float*)d_in[4];
    const float* Wih1 = (const float*)d_in[5];
    const float* Whh1 = (const float*)d_in[6];
    const float* bih1 = (const float*)d_in[7];
    const float* bhh1 = (const float*)d_in[8];
    const float* Wfc  = (const float*)d_in[9];
    const float* bfc  = (const float*)d_in[10];
    float* out = (float*)d_out;

    float *gx, *h1;
    cudaGetSymbolAddress((void**)&gx, g_gx);
    cudaGetSymbolAddress((void**)&h1, g_h1);

    const int smG1 = 2 * (G3 * (DIN0 + 8) * 2) + 4 * (64 * (DIN0 + 8) * 2);
    const int smG2 = 2 * (G3 * (HID + 8) * 2)  + 4 * (64 * (HID + 8) * 2);
    const int smR  = 2 * BBR * PAB + BBR * PHF * 4;   // 17920 B

    cudaFuncSetAttribute(proj_gemm<DIN0>, cudaFuncAttributeMaxDynamicSharedMemorySize, smG1);
    cudaFuncSetAttribute(proj_gemm<HID>,  cudaFuncAttributeMaxDynamicSharedMemorySize, smG2);
    cudaFuncSetAttribute(gru_hmma<true>,  cudaFuncAttributeMaxDynamicSharedMemorySize, smR);
    cudaFuncSetAttribute(gru_hmma<false>, cudaFuncAttributeMaxDynamicSharedMemorySize, smR);

    proj_gemm<DIN0><<<148, 256, smG1>>>(x, Wih0, bih0, gx);
    gru_hmma<true><<<BATCH / BBR, NTR, smR>>>(gx, Whh0, bhh0, nullptr, nullptr, h1, nullptr);
    proj_gemm<HID><<<296, 256, smG2>>>(h1, Wih1, bih1, gx);
    gru_hmma<false><<<BATCH / BBR, NTR, smR>>>(gx, Whh1, bhh1, Wfc, bfc, nullptr, out);
}

// round 10
// speedup vs baseline: 1.0350x; 1.0350x over previous
#include <cuda_runtime.h>
#include <cuda_bf16.h>
#include <cuda_fp16.h>
#include <stdint.h>

#define BATCH 4096
#define SEQT  256
#define DIN0  128
#define HID   64
#define G3    192
#define MTOT  (BATCH * SEQT)   // 1048576 rows

// Scratch (static: no allocations allowed)
__device__ __half g_gx[(long)MTOT * G3];  // 384 MB fp16 gate preactivations (incl b_ih)
__device__ float  g_h1[(long)MTOT * HID]; // layer-1 hidden sequence (fp32)

typedef unsigned long long u64;
typedef unsigned int u32;

// ---------------------------------------------------------------- common
__device__ __forceinline__ void mma16816(float* c, const u32* a, const u32* b) {
    asm volatile(
        "mma.sync.aligned.m16n8k16.row.col.f32.bf16.bf16.f32 "
        "{%0,%1,%2,%3}, {%4,%5,%6,%7}, {%8,%9}, {%0,%1,%2,%3};"
        : "+f"(c[0]), "+f"(c[1]), "+f"(c[2]), "+f"(c[3])
        : "r"(a[0]), "r"(a[1]), "r"(a[2]), "r"(a[3]), "r"(b[0]), "r"(b[1]));
}
__device__ __forceinline__ u32 packhi(float a, float b) {
    return ((u32)__bfloat16_as_ushort(__float2bfloat16(a)))
         | ((u32)__bfloat16_as_ushort(__float2bfloat16(b)) << 16);
}
__device__ __forceinline__ u32 packlo(float a, float b) {
    float al = a - __bfloat162float(__float2bfloat16(a));
    float bl = b - __bfloat162float(__float2bfloat16(b));
    return ((u32)__bfloat16_as_ushort(__float2bfloat16(al)))
         | ((u32)__bfloat16_as_ushort(__float2bfloat16(bl)) << 16);
}
__device__ __forceinline__ float tanha(float x) {
    float y;
    asm("tanh.approx.f32 %0, %1;" : "=f"(y) : "f"(x));
    return y;
}
__device__ __forceinline__ float siga(float x) {       // sigmoid via tanh (1 MUFU)
    return fmaf(0.5f, tanha(0.5f * x), 0.5f);
}

// ================================================================= GEMM
// OUT[m][n] = fp16( sum_k X[m][k] * W[n][k] + bias[n] ), split-bf16 3-term HMMA.
// Persistent; B staged+split once; M=64 tiles, A double-buffered. (core passed R6-R9)
template<int K>
__global__ __launch_bounds__(256, 1)
void proj_gemm(const float* __restrict__ X,
               const float* __restrict__ W,
               const float* __restrict__ bias,
               __half* __restrict__ OUT)
{
    constexpr int P      = K + 8;
    constexpr int NTILES = MTOT / 64;
    constexpr int ABUF   = 64 * P * 2;
    constexpr int BBUF   = G3 * P * 2;
    constexpr int NPF    = K / 16;

    extern __shared__ char smem[];
    char* Bh    = smem;
    char* Bl    = Bh + BBUF;
    char* Abase = Bl + BBUF;

    const int tid = threadIdx.x;
    const int wid = tid >> 5;
    const int lid = tid & 31;
    const int g   = lid >> 2;
    const int cp  = lid & 3;
    const int GRID = gridDim.x;

    for (int c = tid; c < G3 * (K / 8); c += 256) {
        int row = c / (K / 8), k = (c % (K / 8)) * 8;
        const float4* src = (const float4*)(W + row * K + k);
        float4 v0 = src[0], v1 = src[1];
        int byte = (row * P + k) * 2;
        *(uint4*)(Bh + byte) = make_uint4(packhi(v0.x, v0.y), packhi(v0.z, v0.w),
                                          packhi(v1.x, v1.y), packhi(v1.z, v1.w));
        *(uint4*)(Bl + byte) = make_uint4(packlo(v0.x, v0.y), packlo(v0.z, v0.w),
                                          packlo(v1.x, v1.y), packlo(v1.z, v1.w));
    }

    const int mrow = (wid & 1) * 32;
    const int ncol = (wid >> 1) * 48;

    float breg[6][2];
#pragma unroll
    for (int nt = 0; nt < 6; nt++) {
        int col = ncol + nt * 8 + 2 * cp;
        breg[nt][0] = bias[col];
        breg[nt][1] = bias[col + 1];
    }

    float4 pfA[NPF];
    long tile0 = blockIdx.x;
    if (tile0 < NTILES) {
#pragma unroll
        for (int q = 0; q < NPF; q++) {
            int idx = tid + 256 * q;
            int row = idx / (K / 4), k = (idx % (K / 4)) * 4;
            pfA[q] = *(const float4*)(X + (tile0 * 64 + row) * K + k);
        }
        char* Ah = Abase;
        char* Al = Abase + ABUF;
#pragma unroll
        for (int q = 0; q < NPF; q++) {
            int idx = tid + 256 * q;
            int row = idx / (K / 4), k = (idx % (K / 4)) * 4;
            float4 v = pfA[q];
            int byte = (row * P + k) * 2;
            *(uint2*)(Ah + byte) = make_uint2(packhi(v.x, v.y), packhi(v.z, v.w));
            *(uint2*)(Al + byte) = make_uint2(packlo(v.x, v.y), packlo(v.z, v.w));
        }
    }
    __syncthreads();

    int it = 0;
    for (long tile = tile0; tile < NTILES; tile += GRID, it++) {
        const long nxt = tile + GRID;
        if (nxt < NTILES) {
#pragma unroll
            for (int q = 0; q < NPF; q++) {
                int idx = tid + 256 * q;
                int row = idx / (K / 4), k = (idx % (K / 4)) * 4;
                pfA[q] = *(const float4*)(X + (nxt * 64 + row) * K + k);
            }
        }

        char* Ah = Abase + (it & 1) * 2 * ABUF;
        char* Al = Ah + ABUF;

        float acc[2][6][4];
#pragma unroll
        for (int mt = 0; mt < 2; mt++)
#pragma unroll
            for (int nt = 0; nt < 6; nt++)
#pragma unroll
                for (int q = 0; q < 4; q++) acc[mt][nt][q] = 0.0f;

#pragma unroll
        for (int ks = 0; ks < K / 16; ks++) {
            const int kb = ks * 16;
            u32 ahf[2][4], alf[2][4];
#pragma unroll
            for (int mt = 0; mt < 2; mt++) {
                int r = mrow + mt * 16 + g;
                int c0b = (r * P + kb + 2 * cp) * 2;
                int c1b = ((r + 8) * P + kb + 2 * cp) * 2;
                ahf[mt][0] = *(const u32*)(Ah + c0b);
                ahf[mt][1] = *(const u32*)(Ah + c1b);
                ahf[mt][2] = *(const u32*)(Ah + c0b + 16);
                ahf[mt][3] = *(const u32*)(Ah + c1b + 16);
                alf[mt][0] = *(const u32*)(Al + c0b);
                alf[mt][1] = *(const u32*)(Al + c1b);
                alf[mt][2] = *(const u32*)(Al + c0b + 16);
                alf[mt][3] = *(const u32*)(Al + c1b + 16);
            }
            u32 bhf[6][2], blf[6][2];
#pragma unroll
            for (int nt = 0; nt < 6; nt++) {
                int n = ncol + nt * 8 + g;
                int bb = (n * P + kb + 2 * cp) * 2;
                bhf[nt][0] = *(const u32*)(Bh + bb);
                bhf[nt][1] = *(const u32*)(Bh + bb + 16);
                blf[nt][0] = *(const u32*)(Bl + bb);
                blf[nt][1] = *(const u32*)(Bl + bb + 16);
            }
#pragma unroll
            for (int mt = 0; mt < 2; mt++)
#pragma unroll
                for (int nt = 0; nt < 6; nt++) {
                    mma16816(acc[mt][nt], ahf[mt], bhf[nt]);
                    mma16816(acc[mt][nt], ahf[mt], blf[nt]);
                    mma16816(acc[mt][nt], alf[mt], bhf[nt]);
                }
        }

        // ---- stage next tile FIRST (tensor-idle gap filled; epilogue STGs drain after) ----
        if (nxt < NTILES) {
            char* nAh = Abase + ((it + 1) & 1) * 2 * ABUF;
            char* nAl = nAh + ABUF;
#pragma unroll
            for (int q = 0; q < NPF; q++) {
                int idx = tid + 256 * q;
                int row = idx / (K / 4), k = (idx % (K / 4)) * 4;
                float4 v = pfA[q];
                int byte = (row * P + k) * 2;
                *(uint2*)(nAh + byte) = make_uint2(packhi(v.x, v.y), packhi(v.z, v.w));
                *(uint2*)(nAl + byte) = make_uint2(packlo(v.x, v.y), packlo(v.z, v.w));
            }
        }

        // ---- epilogue: fp16 output (half2 per column pair) ----
#pragma unroll
        for (int mt = 0; mt < 2; mt++) {
            long r0 = tile * 64 + mrow + mt * 16 + g;
#pragma unroll
            for (int nt = 0; nt < 6; nt++) {
                int col = ncol + nt * 8 + 2 * cp;
                *(__half2*)(OUT + r0 * G3 + col) =
                    __floats2half2_rn(acc[mt][nt][0] + breg[nt][0], acc[mt][nt][1] + breg[nt][1]);
                *(__half2*)(OUT + (r0 + 8) * G3 + col) =
                    __floats2half2_rn(acc[mt][nt][2] + breg[nt][0], acc[mt][nt][3] + breg[nt][1]);
            }
        }
        __syncthreads();
    }
}

// ============================================================ recurrence (HMMA) — R8 structure
// Per CTA: 32 rows in TWO independent 16-row groups (warps 0-3 / 4-7), named
// barriers + nanosleep stagger. Warp tile m16 x n48; W_hh in B-fragment
// registers (hi/lo bf16, 3-term). gh staged through SMEM; gx read as fp16.
#define BBR 32
#define NTR 256
#define PAB 144                // A-tile byte pitch; conflict-free
#define PG  196                // gh float pitch

template<bool FIRST>
__global__ __launch_bounds__(NTR, 1)
void gru_hmma(const __half* __restrict__ GX,  // [MTOT][G3] fp16 x-part preact + b_ih
              const float* __restrict__ Whh,  // [G3][HID]
              const float* __restrict__ bhh,  // [G3]
              const float* __restrict__ Wfc,
              const float* __restrict__ bfc,
              float* __restrict__ hout,       // FIRST: g_h1
              float* __restrict__ out)        // !FIRST: [BATCH]
{
    extern __shared__ char smemc[];
    char*  sAh = smemc;                        // [32][PAB] bf16 hi
    char*  sAl = sAh + BBR * PAB;              // bf16 lo
    float* sGh = (float*)(sAl + BBR * PAB);    // [32][PG] fp32 gh (incl b_hh)

    const int tid = threadIdx.x;
    const int wid = tid >> 5;
    const int lid = tid & 31;
    const int g   = lid >> 2;
    const int cp  = lid & 3;
    const int b0  = blockIdx.x * BBR;

    const int grp  = wid >> 2;                 // 0 or 1
    const int mrow = grp * 16;                 // group's 16-row base
    const int ncol = (wid & 3) * 48;           // 4 N-warps within group

    // ---- W_hh B-fragments (hi/lo) + b_hh, in registers, loaded once ----
    u32 bh[4][6][2], bl[4][6][2];
    float bhv[6][2];
#pragma unroll
    for (int nt = 0; nt < 6; nt++) {
        int n = ncol + nt * 8 + g;
#pragma unroll
        for (int kc = 0; kc < 4; kc++) {
            int k0 = kc * 16 + 2 * cp;
            float w0 = Whh[n * HID + k0],     w1 = Whh[n * HID + k0 + 1];
            float w2 = Whh[n * HID + k0 + 8], w3 = Whh[n * HID + k0 + 9];
            bh[kc][nt][0] = packhi(w0, w1);  bh[kc][nt][1] = packhi(w2, w3);
            bl[kc][nt][0] = packlo(w0, w1);  bl[kc][nt][1] = packlo(w2, w3);
        }
        int colc = ncol + nt * 8 + 2 * cp;
        bhv[nt][0] = bhh[colc];
        bhv[nt][1] = bhh[colc + 1];
    }

    // ---- gate-side identity (within group): 128 threads own 16 rows x 64 units
    const int gtid = tid & 127;
    const int grow = mrow + (gtid >> 3);       // absolute row 0..31
    const int uc   = gtid & 7;                 // unit block (8 consecutive units)
    const long gxrow0 = ((long)(b0 + grow) * SEQT) * G3 + uc * 8;

    float wfc[8];
    if (!FIRST) {
#pragma unroll
        for (int s = 0; s < 8; s++) wfc[s] = Wfc[uc * 8 + s];
    }
    float hreg[8];
#pragma unroll
    for (int s = 0; s < 8; s++) hreg[s] = 0.0f;

    // zero A tiles (h0 = 0)
    for (int i = tid; i < BBR * PAB / 4; i += NTR) {
        ((u32*)sAh)[i] = 0u;
        ((u32*)sAl)[i] = 0u;
    }
    __syncthreads();

    // prefetch gx(t=0): 3 gates x 8 fp16 units = 3 x uint4 (16B each, aligned)
    uint4 pfh[3];
    {
        const __half* gp = GX + gxrow0;
        pfh[0] = *(const uint4*)(gp);
        pfh[1] = *(const uint4*)(gp + 64);
        pfh[2] = *(const uint4*)(gp + 128);
    }

    if (grp == 1) __nanosleep(400);            // phase stagger
    const u32 barid = grp + 1;                 // named barrier 1 / 2, 128 threads

    for (int t = 0; t < SEQT; t++) {
        // ================= MMA phase: gh = Whh . h =================
        float acc[6][4];
#pragma unroll
        for (int nt = 0; nt < 6; nt++)
#pragma unroll
            for (int q = 0; q < 4; q++) acc[nt][q] = 0.0f;

#pragma unroll
        for (int kc = 0; kc < 4; kc++) {
            const int kb = kc * 16;
            u32 ahf[4], alf[4];
            {
                int r = mrow + g;
                int c0b = r * PAB + (kb + 2 * cp) * 2;
                int c1b = (r + 8) * PAB + (kb + 2 * cp) * 2;
                ahf[0] = *(const u32*)(sAh + c0b);
                ahf[1] = *(const u32*)(sAh + c1b);
                ahf[2] = *(const u32*)(sAh + c0b + 16);
                ahf[3] = *(const u32*)(sAh + c1b + 16);
                alf[0] = *(const u32*)(sAl + c0b);
                alf[1] = *(const u32*)(sAl + c1b);
                alf[2] = *(const u32*)(sAl + c0b + 16);
                alf[3] = *(const u32*)(sAl + c1b + 16);
            }
#pragma unroll
            for (int nt = 0; nt < 6; nt++) {
                mma16816(acc[nt], ahf, bh[kc][nt]);
                mma16816(acc[nt], ahf, bl[kc][nt]);
                mma16816(acc[nt], alf, bh[kc][nt]);
            }
        }
#pragma unroll
        for (int nt = 0; nt < 6; nt++) {
            int col = ncol + nt * 8 + 2 * cp;
            *(float2*)(sGh + (mrow + g) * PG + col) =
                make_float2(acc[nt][0] + bhv[nt][0], acc[nt][1] + bhv[nt][1]);
            *(float2*)(sGh + (mrow + g + 8) * PG + col) =
                make_float2(acc[nt][2] + bhv[nt][0], acc[nt][3] + bhv[nt][1]);
        }
        asm volatile("bar.sync %0, 128;" :: "r"(barid) : "memory");

        // ================= gate phase =================
        {
            const float* gr = sGh + grow * PG + uc * 8;
            float4 r0 = *(const float4*)(gr);
            float4 r1 = *(const float4*)(gr + 4);
            float4 z0 = *(const float4*)(gr + 64);
            float4 z1 = *(const float4*)(gr + 68);
            float4 n0 = *(const float4*)(gr + 128);
            float4 n1 = *(const float4*)(gr + 132);
            float ghr[8] = {r0.x, r0.y, r0.z, r0.w, r1.x, r1.y, r1.z, r1.w};
            float ghz[8] = {z0.x, z0.y, z0.z, z0.w, z1.x, z1.y, z1.z, z1.w};
            float ghn[8] = {n0.x, n0.y, n0.z, n0.w, n1.x, n1.y, n1.z, n1.w};

            // unpack fp16 gx
            float gxr[8], gxz[8], gxn[8];
            {
                const __half2* hr = (const __half2*)&pfh[0];
                const __half2* hz = (const __half2*)&pfh[1];
                const __half2* hn = (const __half2*)&pfh[2];
#pragma unroll
                for (int i = 0; i < 4; i++) {
                    float2 fr = __half22float2(hr[i]);
                    float2 fz = __half22float2(hz[i]);
                    float2 fn = __half22float2(hn[i]);
                    gxr[2 * i] = fr.x; gxr[2 * i + 1] = fr.y;
                    gxz[2 * i] = fz.x; gxz[2 * i + 1] = fz.y;
                    gxn[2 * i] = fn.x; gxn[2 * i + 1] = fn.y;
                }
            }

            float h[8];
#pragma unroll
            for (int s = 0; s < 8; s++) {
                float rg = siga(gxr[s] + ghr[s]);
                float zg = siga(gxz[s] + ghz[s]);
                float ng = tanha(gxn[s] + rg * ghn[s]);
                h[s] = ng + zg * (hreg[s] - ng);
                hreg[s] = h[s];
            }
            int abyte = grow * PAB + uc * 16;
            *(uint4*)(sAh + abyte) = make_uint4(packhi(h[0], h[1]), packhi(h[2], h[3]),
                                                packhi(h[4], h[5]), packhi(h[6], h[7]));
            *(uint4*)(sAl + abyte) = make_uint4(packlo(h[0], h[1]), packlo(h[2], h[3]),
                                                packlo(h[4], h[5]), packlo(h[6], h[7]));
            if (FIRST) {
                float* hp = hout + ((long)(b0 + grow) * SEQT + t) * HID + uc * 8;
                *(float4*)(hp)     = make_float4(h[0], h[1], h[2], h[3]);
                *(float4*)(hp + 4) = make_float4(h[4], h[5], h[6], h[7]);
            }
            if (t + 1 < SEQT) {
                const __half* gp = GX + gxrow0 + (long)(t + 1) * G3;
                pfh[0] = *(const uint4*)(gp);
                pfh[1] = *(const uint4*)(gp + 64);
                pfh[2] = *(const uint4*)(gp + 128);
            }
        }
        asm volatile("bar.sync %0, 128;" :: "r"(barid) : "memory");
    }

    // ---- final FC (layer 2): 8 consecutive threads share a row ----
    if (!FIRST) {
        float s = 0.0f;
#pragma unroll
        for (int q = 0; q < 8; q++) s += hreg[q] * wfc[q];
        s += __shfl_xor_sync(0xFFFFFFFF, s, 1);
        s += __shfl_xor_sync(0xFFFFFFFF, s, 2);
        s += __shfl_xor_sync(0xFFFFFFFF, s, 4);
        if (uc == 0) out[b0 + grow] = s + bfc[0];
    }
}

// ================================================================= host
extern "C" void kernel_launch(void* const* d_in, const int* in_sizes, int n_in,
                              void* d_out, int out_size)
{
    const float* x    = (const float*)d_in[0];
    const float* Wih0 = (const float*)d_in[1];
    const float* Whh0 = (const float*)d_in[2];
    const float* bih0 = (const float*)d_in[3];
    const float* bhh0 = (const float*)d_in[4];
    const float* Wih1 = (const float*)d_in[5];
    const float* Whh1 = (const float*)d_in[6];
    const float* bih1 = (const float*)d_in[7];
    const float* bhh1 = (const float*)d_in[8];
    const float* Wfc  = (const float*)d_in[9];
    const float* bfc  = (const float*)d_in[10];
    float* out = (float*)d_out;

    __half* gx;
    float* h1;
    cudaGetSymbolAddress((void**)&gx, g_gx);
    cudaGetSymbolAddress((void**)&h1, g_h1);

    const int smG1 = 2 * (G3 * (DIN0 + 8) * 2) + 4 * (64 * (DIN0 + 8) * 2);
    const int smG2 = 2 * (G3 * (HID + 8) * 2)  + 4 * (64 * (HID + 8) * 2);
    const int smR  = 2 * BBR * PAB + BBR * PG * 4;

    cudaFuncSetAttribute(proj_gemm<DIN0>, cudaFuncAttributeMaxDynamicSharedMemorySize, smG1);
    cudaFuncSetAttribute(proj_gemm<HID>,  cudaFuncAttributeMaxDynamicSharedMemorySize, smG2);
    cudaFuncSetAttribute(gru_hmma<true>,  cudaFuncAttributeMaxDynamicSharedMemorySize, smR);
    cudaFuncSetAttribute(gru_hmma<false>, cudaFuncAttributeMaxDynamicSharedMemorySize, smR);

    proj_gemm<DIN0><<<148, 256, smG1>>>(x, Wih0, bih0, gx);
    gru_hmma<true><<<BATCH / BBR, NTR, smR>>>(gx, Whh0, bhh0, nullptr, nullptr, h1, nullptr);
    proj_gemm<HID><<<296, 256, smG2>>>(h1, Wih1, bih1, gx);
    gru_hmma<false><<<BATCH / BBR, NTR, smR>>>(gx, Whh1, bhh1, Wfc, bfc, nullptr, out);
}

// round 11
// speedup vs baseline: 1.0521x; 1.0165x over previous
#include <cuda_runtime.h>
#include <cuda_bf16.h>
#include <stdint.h>

#define BATCH 4096
#define SEQT  256
#define DIN0  128
#define HID   64
#define G3    192
#define MTOT  (BATCH * SEQT)   // 1048576 rows

// Scratch (static: no allocations allowed)
__device__ float g_gx[(long)MTOT * G3];   // fp32 gate preactivations incl b_ih (reused both layers)
__device__ float g_h1[(long)MTOT * HID];  // layer-1 hidden sequence

typedef unsigned long long u64;
typedef unsigned int u32;

// ---------------------------------------------------------------- common
__device__ __forceinline__ void mma16816(float* c, const u32* a, const u32* b) {
    asm volatile(
        "mma.sync.aligned.m16n8k16.row.col.f32.bf16.bf16.f32 "
        "{%0,%1,%2,%3}, {%4,%5,%6,%7}, {%8,%9}, {%0,%1,%2,%3};"
        : "+f"(c[0]), "+f"(c[1]), "+f"(c[2]), "+f"(c[3])
        : "r"(a[0]), "r"(a[1]), "r"(a[2]), "r"(a[3]), "r"(b[0]), "r"(b[1]));
}
__device__ __forceinline__ u32 packhi(float a, float b) {
    return ((u32)__bfloat16_as_ushort(__float2bfloat16(a)))
         | ((u32)__bfloat16_as_ushort(__float2bfloat16(b)) << 16);
}
__device__ __forceinline__ u32 packlo(float a, float b) {
    float al = a - __bfloat162float(__float2bfloat16(a));
    float bl = b - __bfloat162float(__float2bfloat16(b));
    return ((u32)__bfloat16_as_ushort(__float2bfloat16(al)))
         | ((u32)__bfloat16_as_ushort(__float2bfloat16(bl)) << 16);
}
__device__ __forceinline__ float tanha(float x) {
    float y;
    asm("tanh.approx.f32 %0, %1;" : "=f"(y) : "f"(x));
    return y;
}
__device__ __forceinline__ float siga(float x) {       // sigmoid via tanh (1 MUFU)
    return fmaf(0.5f, tanha(0.5f * x), 0.5f);
}

// ================================================================= GEMM
// OUT[m][n] = sum_k X[m][k] * W[n][k] + bias[n], split-bf16 3-term HMMA.
// Persistent; B staged+split once; M=64 tiles, A double-buffered. (R8 verbatim)
template<int K>
__global__ __launch_bounds__(256, 1)
void proj_gemm(const float* __restrict__ X,
               const float* __restrict__ W,
               const float* __restrict__ bias,
               float* __restrict__ OUT)
{
    constexpr int P      = K + 8;
    constexpr int NTILES = MTOT / 64;
    constexpr int ABUF   = 64 * P * 2;
    constexpr int BBUF   = G3 * P * 2;
    constexpr int NPF    = K / 16;

    extern __shared__ char smem[];
    char* Bh    = smem;
    char* Bl    = Bh + BBUF;
    char* Abase = Bl + BBUF;

    const int tid = threadIdx.x;
    const int wid = tid >> 5;
    const int lid = tid & 31;
    const int g   = lid >> 2;
    const int cp  = lid & 3;
    const int GRID = gridDim.x;

    for (int c = tid; c < G3 * (K / 8); c += 256) {
        int row = c / (K / 8), k = (c % (K / 8)) * 8;
        const float4* src = (const float4*)(W + row * K + k);
        float4 v0 = src[0], v1 = src[1];
        int byte = (row * P + k) * 2;
        *(uint4*)(Bh + byte) = make_uint4(packhi(v0.x, v0.y), packhi(v0.z, v0.w),
                                          packhi(v1.x, v1.y), packhi(v1.z, v1.w));
        *(uint4*)(Bl + byte) = make_uint4(packlo(v0.x, v0.y), packlo(v0.z, v0.w),
                                          packlo(v1.x, v1.y), packlo(v1.z, v1.w));
    }

    const int mrow = (wid & 1) * 32;
    const int ncol = (wid >> 1) * 48;

    float breg[6][2];
#pragma unroll
    for (int nt = 0; nt < 6; nt++) {
        int col = ncol + nt * 8 + 2 * cp;
        breg[nt][0] = bias[col];
        breg[nt][1] = bias[col + 1];
    }

    float4 pfA[NPF];
    long tile0 = blockIdx.x;
    if (tile0 < NTILES) {
#pragma unroll
        for (int q = 0; q < NPF; q++) {
            int idx = tid + 256 * q;
            int row = idx / (K / 4), k = (idx % (K / 4)) * 4;
            pfA[q] = *(const float4*)(X + (tile0 * 64 + row) * K + k);
        }
        char* Ah = Abase;
        char* Al = Abase + ABUF;
#pragma unroll
        for (int q = 0; q < NPF; q++) {
            int idx = tid + 256 * q;
            int row = idx / (K / 4), k = (idx % (K / 4)) * 4;
            float4 v = pfA[q];
            int byte = (row * P + k) * 2;
            *(uint2*)(Ah + byte) = make_uint2(packhi(v.x, v.y), packhi(v.z, v.w));
            *(uint2*)(Al + byte) = make_uint2(packlo(v.x, v.y), packlo(v.z, v.w));
        }
    }
    __syncthreads();

    int it = 0;
    for (long tile = tile0; tile < NTILES; tile += GRID, it++) {
        const long nxt = tile + GRID;
        if (nxt < NTILES) {
#pragma unroll
            for (int q = 0; q < NPF; q++) {
                int idx = tid + 256 * q;
                int row = idx / (K / 4), k = (idx % (K / 4)) * 4;
                pfA[q] = *(const float4*)(X + (nxt * 64 + row) * K + k);
            }
        }

        char* Ah = Abase + (it & 1) * 2 * ABUF;
        char* Al = Ah + ABUF;

        float acc[2][6][4];
#pragma unroll
        for (int mt = 0; mt < 2; mt++)
#pragma unroll
            for (int nt = 0; nt < 6; nt++)
#pragma unroll
                for (int q = 0; q < 4; q++) acc[mt][nt][q] = 0.0f;

#pragma unroll
        for (int ks = 0; ks < K / 16; ks++) {
            const int kb = ks * 16;
            u32 ahf[2][4], alf[2][4];
#pragma unroll
            for (int mt = 0; mt < 2; mt++) {
                int r = mrow + mt * 16 + g;
                int c0b = (r * P + kb + 2 * cp) * 2;
                int c1b = ((r + 8) * P + kb + 2 * cp) * 2;
                ahf[mt][0] = *(const u32*)(Ah + c0b);
                ahf[mt][1] = *(const u32*)(Ah + c1b);
                ahf[mt][2] = *(const u32*)(Ah + c0b + 16);
                ahf[mt][3] = *(const u32*)(Ah + c1b + 16);
                alf[mt][0] = *(const u32*)(Al + c0b);
                alf[mt][1] = *(const u32*)(Al + c1b);
                alf[mt][2] = *(const u32*)(Al + c0b + 16);
                alf[mt][3] = *(const u32*)(Al + c1b + 16);
            }
            u32 bhf[6][2], blf[6][2];
#pragma unroll
            for (int nt = 0; nt < 6; nt++) {
                int n = ncol + nt * 8 + g;
                int bb = (n * P + kb + 2 * cp) * 2;
                bhf[nt][0] = *(const u32*)(Bh + bb);
                bhf[nt][1] = *(const u32*)(Bh + bb + 16);
                blf[nt][0] = *(const u32*)(Bl + bb);
                blf[nt][1] = *(const u32*)(Bl + bb + 16);
            }
#pragma unroll
            for (int mt = 0; mt < 2; mt++)
#pragma unroll
                for (int nt = 0; nt < 6; nt++) {
                    mma16816(acc[mt][nt], ahf[mt], bhf[nt]);
                    mma16816(acc[mt][nt], ahf[mt], blf[nt]);
                    mma16816(acc[mt][nt], alf[mt], bhf[nt]);
                }
        }

        // stage next tile first (fills tensor-idle gap), then epilogue STGs drain
        if (nxt < NTILES) {
            char* nAh = Abase + ((it + 1) & 1) * 2 * ABUF;
            char* nAl = nAh + ABUF;
#pragma unroll
            for (int q = 0; q < NPF; q++) {
                int idx = tid + 256 * q;
                int row = idx / (K / 4), k = (idx % (K / 4)) * 4;
                float4 v = pfA[q];
                int byte = (row * P + k) * 2;
                *(uint2*)(nAh + byte) = make_uint2(packhi(v.x, v.y), packhi(v.z, v.w));
                *(uint2*)(nAl + byte) = make_uint2(packlo(v.x, v.y), packlo(v.z, v.w));
            }
        }

#pragma unroll
        for (int mt = 0; mt < 2; mt++) {
            long r0 = tile * 64 + mrow + mt * 16 + g;
#pragma unroll
            for (int nt = 0; nt < 6; nt++) {
                int col = ncol + nt * 8 + 2 * cp;
                *(float2*)(OUT + r0 * G3 + col) =
                    make_float2(acc[mt][nt][0] + breg[nt][0], acc[mt][nt][1] + breg[nt][1]);
                *(float2*)(OUT + (r0 + 8) * G3 + col) =
                    make_float2(acc[mt][nt][2] + breg[nt][0], acc[mt][nt][3] + breg[nt][1]);
            }
        }
        __syncthreads();
    }
}

// ============================================================ recurrence (HMMA, wide-N tiling)
// CTA = 16 batch rows, 8 warps; warp w owns n24 (3 n8-tiles at 24w) of the
// single m16 tile -> 36 HMMA per warp per step (halved serial chain).
// grid = 256 -> 108 SMs hold 2 co-resident CTAs whose phases interleave and
// fill each other's dependency stalls. W_hh in B-fragment registers (hi/lo
// bf16, 3-term split: numerics unchanged).
#define BBR 16
#define NTR 256
#define PAB 144                // A-tile byte pitch; words/row = 36 ≡ 4 (mod 32) -> conflict-free
#define PG  196                // gh float pitch

template<bool FIRST>
__global__ __launch_bounds__(NTR, 2)
void gru_hmma(const float* __restrict__ GX,   // [MTOT][G3] x-part preact + b_ih
              const float* __restrict__ Whh,  // [G3][HID]
              const float* __restrict__ bhh,  // [G3]
              const float* __restrict__ Wfc,
              const float* __restrict__ bfc,
              float* __restrict__ hout,       // FIRST: g_h1
              float* __restrict__ out)        // !FIRST: [BATCH]
{
    extern __shared__ char smemc[];
    char*  sAh = smemc;                        // [16][PAB] bf16 hi
    char*  sAl = sAh + BBR * PAB;              // bf16 lo
    float* sGh = (float*)(sAl + BBR * PAB);    // [16][PG] fp32 gh (incl b_hh)

    const int tid = threadIdx.x;
    const int wid = tid >> 5;
    const int lid = tid & 31;
    const int g   = lid >> 2;
    const int cp  = lid & 3;
    const int b0  = blockIdx.x * BBR;

    const int ncol = wid * 24;                 // warp's 24-column slice

    // ---- W_hh B-fragments (hi/lo) + b_hh, registers, loaded once ----
    u32 bh[4][3][2], bl[4][3][2];
    float bhv[3][2];
#pragma unroll
    for (int nt = 0; nt < 3; nt++) {
        int n = ncol + nt * 8 + g;
#pragma unroll
        for (int kc = 0; kc < 4; kc++) {
            int k0 = kc * 16 + 2 * cp;
            float w0 = Whh[n * HID + k0],     w1 = Whh[n * HID + k0 + 1];
            float w2 = Whh[n * HID + k0 + 8], w3 = Whh[n * HID + k0 + 9];
            bh[kc][nt][0] = packhi(w0, w1);  bh[kc][nt][1] = packhi(w2, w3);
            bl[kc][nt][0] = packlo(w0, w1);  bl[kc][nt][1] = packlo(w2, w3);
        }
        int colc = ncol + nt * 8 + 2 * cp;
        bhv[nt][0] = bhh[colc];
        bhv[nt][1] = bhh[colc + 1];
    }

    // ---- gate-side identity: 256 threads own 16 rows x 64 units (4 units each)
    const int grow = tid >> 4;                 // row 0..15
    const int u0   = (tid & 15) * 4;           // 4 consecutive units
    const long gxrow0 = ((long)(b0 + grow) * SEQT) * G3 + u0;

    float wfc[4];
    if (!FIRST) {
#pragma unroll
        for (int s = 0; s < 4; s++) wfc[s] = Wfc[u0 + s];
    }
    float hreg[4];
#pragma unroll
    for (int s = 0; s < 4; s++) hreg[s] = 0.0f;

    // zero A tiles (h0 = 0)
    for (int i = tid; i < BBR * PAB / 4; i += NTR) {
        ((u32*)sAh)[i] = 0u;
        ((u32*)sAl)[i] = 0u;
    }
    __syncthreads();

    // prefetch gx(t=0): 3 gates x 4 units = 3 float4
    float4 pf[3];
    pf[0] = *(const float4*)(GX + gxrow0);
    pf[1] = *(const float4*)(GX + gxrow0 + 64);
    pf[2] = *(const float4*)(GX + gxrow0 + 128);

    for (int t = 0; t < SEQT; t++) {
        // ---------- MMA phase: acc = Whh . h + b_hh ----------
        float acc[3][4];
#pragma unroll
        for (int nt = 0; nt < 3; nt++) {
            acc[nt][0] = bhv[nt][0]; acc[nt][1] = bhv[nt][1];
            acc[nt][2] = bhv[nt][0]; acc[nt][3] = bhv[nt][1];
        }
#pragma unroll
        for (int kc = 0; kc < 4; kc++) {
            const int kb = kc * 16;
            u32 ahf[4], alf[4];
            {
                int c0b = g * PAB + (kb + 2 * cp) * 2;
                int c1b = (g + 8) * PAB + (kb + 2 * cp) * 2;
                ahf[0] = *(const u32*)(sAh + c0b);
                ahf[1] = *(const u32*)(sAh + c1b);
                ahf[2] = *(const u32*)(sAh + c0b + 16);
                ahf[3] = *(const u32*)(sAh + c1b + 16);
                alf[0] = *(const u32*)(sAl + c0b);
                alf[1] = *(const u32*)(sAl + c1b);
                alf[2] = *(const u32*)(sAl + c0b + 16);
                alf[3] = *(const u32*)(sAl + c1b + 16);
            }
#pragma unroll
            for (int nt = 0; nt < 3; nt++) {
                mma16816(acc[nt], ahf, bh[kc][nt]);
                mma16816(acc[nt], ahf, bl[kc][nt]);
                mma16816(acc[nt], alf, bh[kc][nt]);
            }
        }
        // stage gh (D layout validated in proj_gemm epilogue)
#pragma unroll
        for (int nt = 0; nt < 3; nt++) {
            int col = ncol + nt * 8 + 2 * cp;
            *(float2*)(sGh + g * PG + col)       = make_float2(acc[nt][0], acc[nt][1]);
            *(float2*)(sGh + (g + 8) * PG + col) = make_float2(acc[nt][2], acc[nt][3]);
        }
        __syncthreads();

        // ---------- gate phase ----------
        {
            const float* gr = sGh + grow * PG + u0;
            float4 ghr = *(const float4*)(gr);
            float4 ghz = *(const float4*)(gr + 64);
            float4 ghn = *(const float4*)(gr + 128);

            float h[4];
            {
                float rg0 = siga(pf[0].x + ghr.x), rg1 = siga(pf[0].y + ghr.y);
                float rg2 = siga(pf[0].z + ghr.z), rg3 = siga(pf[0].w + ghr.w);
                float zg0 = siga(pf[1].x + ghz.x), zg1 = siga(pf[1].y + ghz.y);
                float zg2 = siga(pf[1].z + ghz.z), zg3 = siga(pf[1].w + ghz.w);
                float ng0 = tanha(pf[2].x + rg0 * ghn.x);
                float ng1 = tanha(pf[2].y + rg1 * ghn.y);
                float ng2 = tanha(pf[2].z + rg2 * ghn.z);
                float ng3 = tanha(pf[2].w + rg3 * ghn.w);
                h[0] = ng0 + zg0 * (hreg[0] - ng0);
                h[1] = ng1 + zg1 * (hreg[1] - ng1);
                h[2] = ng2 + zg2 * (hreg[2] - ng2);
                h[3] = ng3 + zg3 * (hreg[3] - ng3);
                hreg[0] = h[0]; hreg[1] = h[1]; hreg[2] = h[2]; hreg[3] = h[3];
            }
            int abyte = grow * PAB + u0 * 2;
            *(uint2*)(sAh + abyte) = make_uint2(packhi(h[0], h[1]), packhi(h[2], h[3]));
            *(uint2*)(sAl + abyte) = make_uint2(packlo(h[0], h[1]), packlo(h[2], h[3]));

            if (FIRST) {
                float* hp = hout + ((long)(b0 + grow) * SEQT + t) * HID + u0;
                *(float4*)(hp) = make_float4(h[0], h[1], h[2], h[3]);
            }
            if (t + 1 < SEQT) {
                const float* gp = GX + gxrow0 + (long)(t + 1) * G3;
                pf[0] = *(const float4*)(gp);
                pf[1] = *(const float4*)(gp + 64);
                pf[2] = *(const float4*)(gp + 128);
            }
        }
        __syncthreads();
    }

    // ---- final FC (layer 2): 16 threads share a row ----
    if (!FIRST) {
        float s = 0.0f;
#pragma unroll
        for (int q = 0; q < 4; q++) s += hreg[q] * wfc[q];
        s += __shfl_xor_sync(0xFFFFFFFF, s, 1);
        s += __shfl_xor_sync(0xFFFFFFFF, s, 2);
        s += __shfl_xor_sync(0xFFFFFFFF, s, 4);
        s += __shfl_xor_sync(0xFFFFFFFF, s, 8);
        if ((tid & 15) == 0) out[b0 + grow] = s + bfc[0];
    }
}

// ================================================================= host
extern "C" void kernel_launch(void* const* d_in, const int* in_sizes, int n_in,
                              void* d_out, int out_size)
{
    const float* x    = (const float*)d_in[0];
    const float* Wih0 = (const float*)d_in[1];
    const float* Whh0 = (const float*)d_in[2];
    const float* bih0 = (const float*)d_in[3];
    const float* bhh0 = (const float*)d_in[4];
    const float* Wih1 = (const float*)d_in[5];
    const float* Whh1 = (const float*)d_in[6];
    const float* bih1 = (const float*)d_in[7];
    const float* bhh1 = (const float*)d_in[8];
    const float* Wfc  = (const float*)d_in[9];
    const float* bfc  = (const float*)d_in[10];
    float* out = (float*)d_out;

    float *gx, *h1;
    cudaGetSymbolAddress((void**)&gx, g_gx);
    cudaGetSymbolAddress((void**)&h1, g_h1);

    const int smG1 = 2 * (G3 * (DIN0 + 8) * 2) + 4 * (64 * (DIN0 + 8) * 2);
    const int smG2 = 2 * (G3 * (HID + 8) * 2)  + 4 * (64 * (HID + 8) * 2);
    const int smR  = 2 * BBR * PAB + BBR * PG * 4;   // 17152 B -> 2 CTAs/SM

    cudaFuncSetAttribute(proj_gemm<DIN0>, cudaFuncAttributeMaxDynamicSharedMemorySize, smG1);
    cudaFuncSetAttribute(proj_gemm<HID>,  cudaFuncAttributeMaxDynamicSharedMemorySize, smG2);
    cudaFuncSetAttribute(gru_hmma<true>,  cudaFuncAttributeMaxDynamicSharedMemorySize, smR);
    cudaFuncSetAttribute(gru_hmma<false>, cudaFuncAttributeMaxDynamicSharedMemorySize, smR);

    proj_gemm<DIN0><<<148, 256, smG1>>>(x, Wih0, bih0, gx);
    gru_hmma<true><<<BATCH / BBR, NTR, smR>>>(gx, Whh0, bhh0, nullptr, nullptr, h1, nullptr);
    proj_gemm<HID><<<296, 256, smG2>>>(h1, Wih1, bih1, gx);
    gru_hmma<false><<<BATCH / BBR, NTR, smR>>>(gx, Whh1, bhh1, Wfc, bfc, nullptr, out);
}